// round 14
// baseline (speedup 1.0000x reference)
#include <cuda_runtime.h>
#include <cstdint>

#define C_IN  32
#define C_OUT 64
#define KNUM  8
#define TILE  1024
#define NBUF  4
#define NQUAD 4
#define EPS   1e-5f

__device__ float g_sum[C_OUT];
__device__ float g_sumsq[C_OUT];
__device__ unsigned long long g_bar = 0;   // monotonic ticket barrier

// xs first: extern-shared base is 16B+ aligned (cp.async 16B dst requirement).
struct ConvSmem {
    float    xs[NQUAD][NBUF][16][C_IN];   // 32 KB staged x rows (XOR-swizzled)
    uint16_t bins[KNUM][TILE];            // 16 KB tile-local voxel indices
    int      o16[NQUAD][NBUF][16];        // 1 KB  staged out-row indices
    int      cnts[KNUM + 2];
};

__device__ __forceinline__ uint32_t f2tf32(float f) {
    uint32_t r;
    asm("cvt.rna.tf32.f32 %0, %1;" : "=r"(r) : "f"(f));
    return r;
}

// ---------------------------------------------------------------------------
// Pass A: sparse conv + scatter via tf32 mma.sync (m16n8k8). (R13, proven.)
// 512 threads = 4 warp-quads, 2 CTAs/SM. Quad q handles bins q and q+4;
// warp w of a quad computes channels [16w, 16w+16) (W fragments 16 regs).
// x rows cp.async-staged, ring of 4 buffers, prefetch distance 2.
// ---------------------------------------------------------------------------
__global__ void __launch_bounds__(512, 2)
conv_scatter(const float* __restrict__ x,
             const float* __restrict__ W,
             const int*   __restrict__ kidx,
             const int*   __restrict__ oidx,
             float*       __restrict__ out,
             int n)
{
    extern __shared__ char smem_raw[];
    ConvSmem* sm = reinterpret_cast<ConvSmem*>(smem_raw);

    const int tid  = threadIdx.x;
    const int lane = tid & 31;
    const int wid  = tid >> 5;       // 0..15
    const int quad = wid >> 2;       // 0..3
    const int w4   = wid & 3;        // warp within quad

    if (blockIdx.x == 0 && tid < C_OUT) { g_sum[tid] = 0.f; g_sumsq[tid] = 0.f; }

    const int rl = lane >> 2;        // 0..7
    const int e  = lane & 3;         // 0..3

    const int tileBase = blockIdx.x * TILE;
    if (tid < KNUM + 2) sm->cnts[tid] = 0;
    __syncthreads();

    #pragma unroll
    for (int u = 0; u < TILE / 512; ++u) {
        int  loc   = u * 512 + tid;
        int  i     = tileBase + loc;
        bool valid = (i < n);
        int  k     = valid ? kidx[i] : KNUM;
        unsigned mask   = __match_any_sync(0xffffffffu, k);
        int      leader = __ffs(mask) - 1;
        int      rank   = __popc(mask & ((1u << lane) - 1u));
        int      base   = 0;
        if (lane == leader) base = atomicAdd(&sm->cnts[k], __popc(mask));
        base = __shfl_sync(0xffffffffu, base, leader);
        if (valid) sm->bins[k][base + rank] = (uint16_t)loc;
    }
    __syncthreads();

    const int cnt_a = sm->cnts[quad];
    const int cnt_b = sm->cnts[quad + NQUAD];
    const int na    = (cnt_a + 15) >> 4;
    const int nb    = (cnt_b + 15) >> 4;
    const int ntot  = na + nb;
    if (ntot == 0) return;

    const uint32_t xs_smem =
        (uint32_t)__cvta_generic_to_shared(&sm->xs[quad][0][0][0]);

    auto decode = [&](int t, int& jj, int& base, int& cntj) {
        if (t < na) { jj = quad;         base = t * 16;        cntj = cnt_a; }
        else        { jj = quad + NQUAD; base = (t - na) * 16; cntj = cnt_b; }
    };

    auto stage = [&](int t, int buf) {
        if (t < ntot) {
            int jj, base, cntj; decode(t, jj, base, cntj);
            const int s   = 4 * w4 + (lane >> 3);
            const int idx = base + s;
            if (idx < cntj) {
                int i = tileBase + (int)sm->bins[jj][idx];
                int g = lane & 7;
                const float* src = x + (size_t)i * C_IN + g * 4;
                uint32_t fc  = (uint32_t)((g * 4) ^ ((s & 7) << 2));
                uint32_t dst = xs_smem +
                    (uint32_t)(buf * 16 * C_IN + s * C_IN + fc) * 4u;
                asm volatile("cp.async.ca.shared.global [%0], [%1], 16;"
                             :: "r"(dst), "l"(src));
            }
            if (w4 == 0 && lane < 16) {
                int idx2 = base + lane;
                sm->o16[quad][buf][lane] =
                    (idx2 < cntj) ? oidx[tileBase + (int)sm->bins[jj][idx2]] : 0;
            }
        }
        asm volatile("cp.async.commit_group;");
    };

    uint32_t bf[4][2][2];
    int cur_bin = -1;
    auto load_bf = [&](int jj) {
        const float* Wj = W + jj * (C_IN * C_OUT);
        #pragma unroll
        for (int kt = 0; kt < 4; ++kt)
            #pragma unroll
            for (int nt = 0; nt < 2; ++nt) {
                int col = 16 * w4 + nt * 8 + rl;
                bf[kt][nt][0] = f2tf32(Wj[(kt * 8 + e)     * C_OUT + col]);
                bf[kt][nt][1] = f2tf32(Wj[(kt * 8 + e + 4) * C_OUT + col]);
            }
    };

    stage(0, 0);
    stage(1, 1);

    for (int t = 0; t < ntot; ++t) {
        const int buf = t & 3;
        stage(t + 2, (t + 2) & 3);
        asm volatile("cp.async.wait_group 2;");
        asm volatile("bar.sync %0, 128;" :: "r"(quad + 1));

        int jj, base, cntj; decode(t, jj, base, cntj);
        if (jj != cur_bin) { load_bf(jj); cur_bin = jj; }

        const int  oa = sm->o16[quad][buf][rl];
        const int  ob = sm->o16[quad][buf][rl + 8];
        const bool va = (base + rl)     < cntj;
        const bool vb = (base + rl + 8) < cntj;

        float c[2][4];
        #pragma unroll
        for (int nt = 0; nt < 2; ++nt)
            c[nt][0] = c[nt][1] = c[nt][2] = c[nt][3] = 0.f;

        const float* xb = &sm->xs[quad][buf][0][0];
        #pragma unroll
        for (int kt = 0; kt < 4; ++kt) {
            int c0 = (kt * 8 + e)     ^ (rl << 2);
            int c4 = (kt * 8 + 4 + e) ^ (rl << 2);
            uint32_t a0 = f2tf32(xb[rl * C_IN + c0]);
            uint32_t a1 = f2tf32(xb[(rl + 8) * C_IN + c0]);
            uint32_t a2 = f2tf32(xb[rl * C_IN + c4]);
            uint32_t a3 = f2tf32(xb[(rl + 8) * C_IN + c4]);
            #pragma unroll
            for (int nt = 0; nt < 2; ++nt) {
                asm volatile(
                    "mma.sync.aligned.m16n8k8.row.col.f32.tf32.tf32.f32 "
                    "{%0,%1,%2,%3}, {%4,%5,%6,%7}, {%8,%9}, {%0,%1,%2,%3};"
                    : "+f"(c[nt][0]), "+f"(c[nt][1]),
                      "+f"(c[nt][2]), "+f"(c[nt][3])
                    : "r"(a0), "r"(a1), "r"(a2), "r"(a3),
                      "r"(bf[kt][nt][0]), "r"(bf[kt][nt][1]));
            }
        }

        #pragma unroll
        for (int nt = 0; nt < 2; ++nt) {
            int coloff = 16 * w4 + nt * 8 + (e << 1);
            if (va) atomicAdd((float2*)(out + (size_t)oa * C_OUT + coloff),
                              make_float2(c[nt][0], c[nt][1]));
            if (vb) atomicAdd((float2*)(out + (size_t)ob * C_OUT + coloff),
                              make_float2(c[nt][2], c[nt][3]));
        }
    }
    asm volatile("cp.async.wait_group 0;");
}

// ---------------------------------------------------------------------------
// Pass B (fused): stats -> grid barrier -> per-thread BN coeffs -> norm+ReLU.
// Persistent exactly-resident grid (__launch_bounds__(256, 8), grid from the
// occupancy API). Each block owns a contiguous 16-aligned slab of float4s so
// the norm phase re-reads its own slab while it is still L2-resident.
// Ticket barrier: monotonic u64 counter, correct across CUDA-graph replays.
// ---------------------------------------------------------------------------
__global__ void __launch_bounds__(256, 8)
stats_norm(float4* __restrict__ out4, int n4,
           const float* __restrict__ gamma,
           const float* __restrict__ beta,
           float inv_n, int nblk)
{
    // 16-aligned contiguous slab for this block.
    int per = (((n4 + nblk - 1) / nblk) + 15) & ~15;
    int lo  = blockIdx.x * per;
    int hi  = lo + per; if (hi > n4) hi = n4;

    // ---- Phase 1: per-slab channel sums ----
    float4 s  = make_float4(0.f, 0.f, 0.f, 0.f);
    float4 s2 = make_float4(0.f, 0.f, 0.f, 0.f);
    for (int i = lo + threadIdx.x; i < hi; i += 256) {
        float4 v = out4[i];
        s.x += v.x; s.y += v.y; s.z += v.z; s.w += v.w;
        s2.x = fmaf(v.x, v.x, s2.x);
        s2.y = fmaf(v.y, v.y, s2.y);
        s2.z = fmaf(v.z, v.z, s2.z);
        s2.w = fmaf(v.w, v.w, s2.w);
    }

    __shared__ float sh1[C_OUT], sh2[C_OUT];
    if (threadIdx.x < C_OUT) { sh1[threadIdx.x] = 0.f; sh2[threadIdx.x] = 0.f; }
    __syncthreads();
    // lo and 256 are multiples of 16 -> channel group fixed per thread.
    const int cg = (threadIdx.x & 15) * 4;
    atomicAdd(&sh1[cg + 0], s.x);  atomicAdd(&sh1[cg + 1], s.y);
    atomicAdd(&sh1[cg + 2], s.z);  atomicAdd(&sh1[cg + 3], s.w);
    atomicAdd(&sh2[cg + 0], s2.x); atomicAdd(&sh2[cg + 1], s2.y);
    atomicAdd(&sh2[cg + 2], s2.z); atomicAdd(&sh2[cg + 3], s2.w);
    __syncthreads();
    if (threadIdx.x < C_OUT) {
        atomicAdd(&g_sum[threadIdx.x],   sh1[threadIdx.x]);
        atomicAdd(&g_sumsq[threadIdx.x], sh2[threadIdx.x]);
    }

    // ---- Grid barrier (ticket-based, replay-safe) ----
    __threadfence();
    __syncthreads();
    if (threadIdx.x == 0) {
        unsigned long long t = atomicAdd(&g_bar, 1ULL);
        unsigned long long target =
            (t / (unsigned long long)nblk + 1ULL) * (unsigned long long)nblk;
        unsigned long long v;
        do {
            asm volatile("ld.global.acquire.gpu.u64 %0, [%1];"
                         : "=l"(v) : "l"(&g_bar));
        } while (v < target);
    }
    __syncthreads();

    // ---- Phase 2: per-thread BN coefficients (no second barrier) ----
    float4 av, bv;
    {
        float m, var, a;
        #pragma unroll
        for (int u = 0; u < 4; ++u) {
            int c = cg + u;
            m   = g_sum[c] * inv_n;
            var = g_sumsq[c] * inv_n - m * m;
            a   = gamma[c] * rsqrtf(var + EPS);
            float b = fmaf(-m, a, beta[c]);
            if (u == 0) { av.x = a; bv.x = b; }
            if (u == 1) { av.y = a; bv.y = b; }
            if (u == 2) { av.z = a; bv.z = b; }
            if (u == 3) { av.w = a; bv.w = b; }
        }
    }

    // ---- Phase 3: normalize + ReLU over the same (L2-hot) slab ----
    for (int i = lo + threadIdx.x; i < hi; i += 256) {
        float4 v = out4[i];
        v.x = fmaxf(fmaf(v.x, av.x, bv.x), 0.f);
        v.y = fmaxf(fmaf(v.y, av.y, bv.y), 0.f);
        v.z = fmaxf(fmaf(v.z, av.z, bv.z), 0.f);
        v.w = fmaxf(fmaf(v.w, av.w, bv.w), 0.f);
        out4[i] = v;
    }
}

// ---------------------------------------------------------------------------
// Launch. Inputs: x, W, bias, gamma, beta, k_idx, out_idx, num_out.
// ---------------------------------------------------------------------------
extern "C" void kernel_launch(void* const* d_in, const int* in_sizes, int n_in,
                              void* d_out, int out_size)
{
    const float* x     = (const float*)d_in[0];
    const float* W     = (const float*)d_in[1];
    const float* gamma = (const float*)d_in[3];
    const float* beta  = (const float*)d_in[4];
    const int*   kidx  = (const int*)d_in[5];
    const int*   oidx  = (const int*)d_in[6];

    const int n       = in_sizes[0] / C_IN;
    const int total   = out_size;               // num_out * 64
    const int num_out = total / C_OUT;
    const int n4      = total / 4;

    const int smem_bytes = (int)sizeof(ConvSmem);   // ~50 KB (2 CTAs/SM)
    cudaFuncSetAttribute(conv_scatter,
                         cudaFuncAttributeMaxDynamicSharedMemorySize,
                         smem_bytes);

    // Exactly-resident grid for the fused stats/norm kernel (barrier safety).
    int blocks_per_sm = 0, sms = 0;
    cudaOccupancyMaxActiveBlocksPerMultiprocessor(&blocks_per_sm, stats_norm,
                                                  256, 0);
    cudaDeviceGetAttribute(&sms, cudaDevAttrMultiProcessorCount, 0);
    int nblk = blocks_per_sm * sms;
    if (nblk < 1) nblk = 1;

    cudaMemsetAsync(d_out, 0, (size_t)total * sizeof(float), 0);

    const int tiles = (n + TILE - 1) / TILE;
    conv_scatter<<<tiles, 512, smem_bytes>>>(x, W, kidx, oidx, (float*)d_out, n);
    stats_norm<<<nblk, 256>>>((float4*)d_out, n4, gamma, beta,
                              1.0f / (float)num_out, nblk);
}